// round 13
// baseline (speedup 1.0000x reference)
#include <cuda_runtime.h>
#include <cuda_bf16.h>
#include <cstdint>
#include <cstddef>

#define T_STEPS 512
#define BATCH   32
#define HID     1024
#define GDIM    4096
#define MROWS   16384          // T*B
#define YW      2048           // 2*H

typedef unsigned long long ull;

// ---------------- device scratch (no runtime allocation) ----------------
__device__ float g_gx[134217728];        // [2][MROWS][GDIM]  512 MB
__device__ __nv_bfloat16 g_hB[2][2][2][32 * 1024]; // [dir][parity][plane][b*1024+k]
__device__ unsigned g_bar_cnt[2]   = {0, 0};
__device__ unsigned g_bar_phase[2] = {0, 0};
// bf16 split planes for input GEMM
__device__ __nv_bfloat16 g_whi[36700160];   // w_ih hi (all 6)
__device__ __nv_bfloat16 g_wlo[36700160];   // w_ih lo
__device__ __nv_bfloat16 g_ahi[33554432];   // activations hi
__device__ __nv_bfloat16 g_alo[33554432];   // activations lo
// W_hh baked per-thread fragment streams (8 warps = 2 m-halves x 4 K-quarters):
// [ld 6][cb 64][wr 8][kt 16][lane 32] x 64B {hi(mi0), lo(mi0), hi(mi1), lo(mi1)}
__device__ uint4 g_wrec[6291456];           // 100.66 MB

// ---------------- helpers ----------------
__device__ __forceinline__ uint32_t smem_u32(const void* p) {
    uint32_t a;
    asm("{ .reg .u64 t; cvta.to.shared.u64 t, %1; cvt.u32.u64 %0, t; }" : "=r"(a) : "l"(p));
    return a;
}
#define SW128(o) ((o) ^ (((o) >> 3) & 0x70))

#define MMA_BF16(d, a, b0v, b1v)                                              \
    asm volatile("mma.sync.aligned.m16n8k16.row.col.f32.bf16.bf16.f32 "       \
        "{%0,%1,%2,%3}, {%4,%5,%6,%7}, {%8,%9}, {%0,%1,%2,%3};"               \
        : "+f"((d)[0]), "+f"((d)[1]), "+f"((d)[2]), "+f"((d)[3])              \
        : "r"((a)[0]), "r"((a)[1]), "r"((a)[2]), "r"((a)[3]),                 \
          "r"(b0v), "r"(b1v))

#define LDSM4(r, addr)                                                        \
    asm volatile("ldmatrix.sync.aligned.m8n8.x4.shared.b16 "                  \
        "{%0,%1,%2,%3}, [%4];"                                                \
        : "=r"((r)[0]), "=r"((r)[1]), "=r"((r)[2]), "=r"((r)[3])              \
        : "r"(addr))

#define CP_ASYNC16(smaddr, gaddr)                                             \
    asm volatile("cp.async.cg.shared.global [%0], [%1], 16;"                  \
        :: "r"(smaddr), "l"(gaddr) : "memory")
#define CP_COMMIT() asm volatile("cp.async.commit_group;" ::: "memory")
#define CP_WAIT0()  asm volatile("cp.async.wait_group 0;" ::: "memory")
#define CP_WAIT1()  asm volatile("cp.async.wait_group 1;" ::: "memory")

__device__ __forceinline__ float hsig(float v)  { return fminf(fmaxf(fmaf(v, 0.2f, 0.5f), 0.0f), 1.0f); }
__device__ __forceinline__ float clip1(float v) { return fminf(fmaxf(v, -1.0f), 1.0f); }

// sense-reversing grid barrier: release/acquire atomics, nanosleep backoff.
__device__ __forceinline__ void grid_barrier(int dir, unsigned& sense) {
    __syncthreads();
    sense ^= 1u;
    if (threadIdx.x == 0) {
        unsigned prev;
        asm volatile("atom.add.acq_rel.gpu.u32 %0, [%1], 1;"
                     : "=r"(prev) : "l"(&g_bar_cnt[dir]) : "memory");
        if (prev == 63u) {
            asm volatile("st.relaxed.gpu.u32 [%0], %1;"
                         :: "l"(&g_bar_cnt[dir]), "r"(0u) : "memory");
            unsigned dummy;
            asm volatile("atom.exch.release.gpu.b32 %0, [%1], %2;"
                         : "=r"(dummy) : "l"(&g_bar_phase[dir]), "r"(sense) : "memory");
        } else {
            unsigned ph;
            do {
                __nanosleep(64);
                asm volatile("ld.acquire.gpu.u32 %0, [%1];"
                             : "=r"(ph) : "l"(&g_bar_phase[dir]) : "memory");
            } while (ph != sense);
        }
    }
    __syncthreads();
}

// ---------------- W_hh prep: bake per-thread fragment streams ----------------
// Rec warp layout: wr(0..7) -> mh = wr>>2 (m half), kq = wr&3 (K quarter).
// Warp covers m32 = gate tiles {mh*2, mh*2+1}, K256 = [kq*256, kq*256+256).
// Per (kt,lane): 4 uint4 = {hi(ml=0), lo(ml=0), hi(ml=1), lo(ml=1)}.
struct W6 { const float* w[6]; };

__global__ void __launch_bounds__(256)
wrec_prep(W6 p, uint4* __restrict__ out)
{
    const int cb = blockIdx.x;
    const int ld = blockIdx.y;
    const float* __restrict__ w = p.w[ld];
    for (int it = 0; it < 32; it++) {
        int v    = it * 256 + threadIdx.x;   // 0..8191 = 8 wr x 16 kt x 32 lanes x 2 ml
        int wr   = v >> 10;                  // warp 0..7
        int kt   = (v >> 6) & 15;
        int lane = (v >> 1) & 31;
        int ml   = v & 1;
        int mh = wr >> 2, kq = wr & 3;
        int mi = mh * 2 + ml;
        unsigned short hi[8], lo[8];
#pragma unroll
        for (int j = 0; j < 4; j++) {
            int r  = (lane >> 2) + (j & 1) * 8;
            int kc = (lane & 3) * 2 + (j >> 1) * 8;
            int row = mi * HID + cb * 16 + r;
            int k   = kq * 256 + kt * 16 + kc;
#pragma unroll
            for (int e = 0; e < 2; e++) {
                float f = w[(size_t)row * HID + k + e];
                __nv_bfloat16 h = __float2bfloat16_rn(f);
                __nv_bfloat16 l = __float2bfloat16_rn(f - __bfloat162float(h));
                hi[j * 2 + e] = *(unsigned short*)&h;
                lo[j * 2 + e] = *(unsigned short*)&l;
            }
        }
        size_t idx = ((((size_t)(ld * 64 + cb) * 8 + wr) * 16 + kt) * 32 + lane) * 4 + ml * 2;
        out[idx]     = *(uint4*)hi;
        out[idx + 1] = *(uint4*)lo;
    }
}

// ---------------- w_ih split: all 6 weights in one launch ----------------
__global__ void __launch_bounds__(256)
wih_split(W6 p, __nv_bfloat16* __restrict__ hi_base, __nv_bfloat16* __restrict__ lo_base)
{
    const int ld = blockIdx.y;
    const size_t woff = (ld == 0) ? 0u :
                        (ld == 1) ? 1310720u :
                        (size_t)2621440u + (size_t)(ld - 2) * 8388608u;
    const int n4 = (ld < 2) ? 327680 : 2097152;
    int i = blockIdx.x * 256 + threadIdx.x;
    if (i >= n4) return;
    const float4* src = (const float4*)p.w[ld];
    float4 v = src[i];
    __nv_bfloat16 h0 = __float2bfloat16_rn(v.x);
    __nv_bfloat16 h1 = __float2bfloat16_rn(v.y);
    __nv_bfloat16 h2 = __float2bfloat16_rn(v.z);
    __nv_bfloat16 h3 = __float2bfloat16_rn(v.w);
    __nv_bfloat16 l0 = __float2bfloat16_rn(v.x - __bfloat162float(h0));
    __nv_bfloat16 l1 = __float2bfloat16_rn(v.y - __bfloat162float(h1));
    __nv_bfloat16 l2 = __float2bfloat16_rn(v.z - __bfloat162float(h2));
    __nv_bfloat16 l3 = __float2bfloat16_rn(v.w - __bfloat162float(h3));
    __nv_bfloat162* H = (__nv_bfloat162*)(hi_base + woff) + i * 2;
    __nv_bfloat162* L = (__nv_bfloat162*)(lo_base + woff) + i * 2;
    H[0] = __nv_bfloat162(h0, h1); H[1] = __nv_bfloat162(h2, h3);
    L[0] = __nv_bfloat162(l0, l1); L[1] = __nv_bfloat162(l2, l3);
}

// ---------------- tensor-core input-projection GEMM (2-stage cp.async pipeline) ----------------
#define SMO_AHI 0
#define SMO_ALO 16384
#define SMO_BHI 32768
#define SMO_BLO 49152
#define STAGE_BYTES 65536
#define SMO_BIAS 131072
#define GEMM_SMEM (131072 + 512)

__global__ void __launch_bounds__(256)
gemm_mma(int K, const float* __restrict__ Afp,
         const __nv_bfloat16* __restrict__ Ahi, const __nv_bfloat16* __restrict__ Alo,
         const __nv_bfloat16* __restrict__ WhiF, const __nv_bfloat16* __restrict__ WloF,
         const __nv_bfloat16* __restrict__ WhiR, const __nv_bfloat16* __restrict__ WloR,
         const float* __restrict__ bf1, const float* __restrict__ bf2,
         const float* __restrict__ br1, const float* __restrict__ br2,
         float* __restrict__ G)
{
    extern __shared__ char sm[];
    const uint32_t smb = smem_u32(sm);
    const int tid  = threadIdx.x;
    const int wid  = tid >> 5;
    const int lane = tid & 31;
    const int z    = blockIdx.z;

    const __nv_bfloat16* __restrict__ Whi = z ? WhiR : WhiF;
    const __nv_bfloat16* __restrict__ Wlo = z ? WloR : WloF;
    const float* __restrict__ b1 = z ? br1 : bf1;
    const float* __restrict__ b2 = z ? br2 : bf2;
    float* __restrict__ Gz = G + (size_t)z * MROWS * GDIM;

    const int n0 = blockIdx.x * 128;
    const int m0 = blockIdx.y * 128;
    const int wm = (wid >> 2) * 64;
    const int wn = (wid & 3) * 32;

    {
        float* bias = (float*)(sm + SMO_BIAS);
        if (tid < 128) bias[tid] = b1[n0 + tid] + b2[n0 + tid];
    }

    float acc[4][4][4];
#pragma unroll
    for (int mi = 0; mi < 4; mi++)
#pragma unroll
        for (int ni = 0; ni < 4; ni++)
#pragma unroll
            for (int e = 0; e < 4; e++) acc[mi][ni][e] = 0.0f;

    const int nk = K >> 6;

    int srow[4], scol[4];
    uint32_t soff[4];
#pragma unroll
    for (int i = 0; i < 4; i++) {
        int v = tid + i * 256;
        srow[i] = v >> 3;
        scol[i] = (v & 7) * 8;
        soff[i] = SW128((uint32_t)(srow[i] * 128 + (v & 7) * 16));
    }

#define GEMM_MMA_CHUNK(SB)                                                    \
    {                                                                         \
        _Pragma("unroll")                                                     \
        for (int ks = 0; ks < 4; ks++) {                                      \
            uint32_t ah[4][4], al[4][4], bh[2][4], bl[2][4];                  \
            _Pragma("unroll")                                                 \
            for (int mi = 0; mi < 4; mi++) {                                  \
                uint32_t off = SW128((uint32_t)(                              \
                    (wm + mi * 16 + (lane & 15)) * 128 + ks * 32 + (lane >> 4) * 16)); \
                LDSM4(ah[mi], smb + (SB) + SMO_AHI + off);                    \
                LDSM4(al[mi], smb + (SB) + SMO_ALO + off);                    \
            }                                                                 \
            _Pragma("unroll")                                                 \
            for (int p = 0; p < 2; p++) {                                     \
                int q  = lane >> 3;                                           \
                int nf = q >> 1, kl = q & 1;                                  \
                uint32_t off = SW128((uint32_t)(                              \
                    (wn + p * 16 + nf * 8 + (lane & 7)) * 128 + ks * 32 + kl * 16)); \
                LDSM4(bh[p], smb + (SB) + SMO_BHI + off);                     \
                LDSM4(bl[p], smb + (SB) + SMO_BLO + off);                     \
            }                                                                 \
            _Pragma("unroll")                                                 \
            for (int mi = 0; mi < 4; mi++) {                                  \
                _Pragma("unroll")                                             \
                for (int ni = 0; ni < 4; ni++) {                              \
                    const int p = ni >> 1, s = (ni & 1) * 2;                  \
                    MMA_BF16(acc[mi][ni], ah[mi], bh[p][s], bh[p][s + 1]);    \
                    MMA_BF16(acc[mi][ni], ah[mi], bl[p][s], bl[p][s + 1]);    \
                    MMA_BF16(acc[mi][ni], al[mi], bh[p][s], bh[p][s + 1]);    \
                }                                                             \
            }                                                                 \
        }                                                                     \
    }

    if (Afp) {
        for (int ch = 0; ch < nk; ch++) {
            const int kc = ch * 64;
            __syncthreads();
#pragma unroll
            for (int i = 0; i < 4; i++) {
                size_t ga = (size_t)(m0 + srow[i]) * K + kc + scol[i];
                size_t gb = (size_t)(n0 + srow[i]) * K + kc + scol[i];
                float4 f0 = *(const float4*)(Afp + ga);
                float4 f1 = *(const float4*)(Afp + ga + 4);
                float fv[8] = {f0.x, f0.y, f0.z, f0.w, f1.x, f1.y, f1.z, f1.w};
                unsigned short hh[8], ll[8];
#pragma unroll
                for (int j = 0; j < 8; j++) {
                    __nv_bfloat16 h = __float2bfloat16_rn(fv[j]);
                    __nv_bfloat16 l = __float2bfloat16_rn(fv[j] - __bfloat162float(h));
                    hh[j] = *(unsigned short*)&h;
                    ll[j] = *(unsigned short*)&l;
                }
                *(uint4*)(sm + SMO_AHI + soff[i]) = *(uint4*)hh;
                *(uint4*)(sm + SMO_ALO + soff[i]) = *(uint4*)ll;
                *(uint4*)(sm + SMO_BHI + soff[i]) = *(const uint4*)(Whi + gb);
                *(uint4*)(sm + SMO_BLO + soff[i]) = *(const uint4*)(Wlo + gb);
            }
            __syncthreads();
            GEMM_MMA_CHUNK(0u)
        }
    } else {
#define GEMM_STAGE(CH, PB)                                                    \
        {                                                                     \
            const int kc_ = (CH) * 64;                                        \
            const uint32_t sb_ = (uint32_t)(PB) * STAGE_BYTES;                \
            _Pragma("unroll")                                                 \
            for (int i = 0; i < 4; i++) {                                     \
                size_t ga = (size_t)(m0 + srow[i]) * K + kc_ + scol[i];       \
                size_t gb = (size_t)(n0 + srow[i]) * K + kc_ + scol[i];       \
                CP_ASYNC16(smb + sb_ + SMO_AHI + soff[i], Ahi + ga);          \
                CP_ASYNC16(smb + sb_ + SMO_ALO + soff[i], Alo + ga);          \
                CP_ASYNC16(smb + sb_ + SMO_BHI + soff[i], Whi + gb);          \
                CP_ASYNC16(smb + sb_ + SMO_BLO + soff[i], Wlo + gb);          \
            }                                                                 \
        }
        GEMM_STAGE(0, 0)
        CP_COMMIT();
        for (int ch = 0; ch < nk; ch++) {
            if (ch + 1 < nk) {
                GEMM_STAGE(ch + 1, (ch + 1) & 1)
                CP_COMMIT();
                CP_WAIT1();
            } else {
                CP_WAIT0();
            }
            __syncthreads();
            const uint32_t sb = (uint32_t)(ch & 1) * STAGE_BYTES;
            GEMM_MMA_CHUNK(sb)
            __syncthreads();
        }
#undef GEMM_STAGE
    }

    const float* bias = (const float*)(sm + SMO_BIAS);
    const int qr = lane >> 2;
    const int qc = (lane & 3) * 2;
#pragma unroll
    for (int mi = 0; mi < 4; mi++) {
#pragma unroll
        for (int ni = 0; ni < 4; ni++) {
            int col = wn + ni * 8 + qc;
            float bx = bias[col], by = bias[col + 1];
            size_t base0 = (size_t)(m0 + wm + mi * 16 + qr) * GDIM + n0 + col;
            size_t base1 = base0 + (size_t)8 * GDIM;
            *(float2*)&Gz[base0] = make_float2(acc[mi][ni][0] + bx, acc[mi][ni][1] + by);
            *(float2*)&Gz[base1] = make_float2(acc[mi][ni][2] + bx, acc[mi][ni][3] + by);
        }
    }
}

// ---------------- persistent tensor-core recurrence (m32 warps, K-quarters) ----------------
// 128 CTAs x 256 threads. dir = blockIdx.x>>6; CTA owns 16 units (64 gate rows).
// Warp wr: mh = wr>>2 (m half, 2 gate tiles), kq = wr&3 (K quarter, 16 kt).
// B LDSM shared across 2 mi (2x dedup); W depth-4 kt register ring (latency hidden).
#define RSM_HA 0
#define RSM_HB 65536
#define RSM_G  131072
#define REC3_SMEM (131072 + 4*64*33*4)   // 164864 B

__global__ void __launch_bounds__(256)
rec_kernel(const uint4* __restrict__ wrec,
           const float* __restrict__ h0, const float* __restrict__ c0,
           int layer, const float* __restrict__ gx,
           float* __restrict__ yfp,
           __nv_bfloat16* __restrict__ yhi, __nv_bfloat16* __restrict__ ylo)
{
    extern __shared__ char sm[];
    const uint32_t smb = smem_u32(sm);
    float* Gp = (float*)(sm + RSM_G);          // 4 x [64][33] K-quarter partials

    const int tid  = threadIdx.x;
    const int lane = tid & 31;
    const int wr   = tid >> 5;                 // warp 0..7
    const int mh   = wr >> 2;                  // m half
    const int kq   = wr & 3;                   // K quarter
    const int dir  = blockIdx.x >> 6;
    const int cb   = blockIdx.x & 63;
    const int ld   = layer * 2 + dir;
    const float* __restrict__ gxd = gx + (size_t)dir * MROWS * GDIM;
    // stream per (ld,cb,wr): 16 kt x 32 lanes x 4 = 2048 uint4; per-kt advance 128
    const uint4* __restrict__ wfrag =
        wrec + ((size_t)(ld * 64 + cb) * 8 + wr) * 2048 + lane * 4;

    // c-state: 2 (unit,batch) pairs per thread
    float cst[2];
    int uu[2], bb[2];
#pragma unroll
    for (int q = 0; q < 2; q++) {
        int p = q * 256 + tid;
        uu[q] = p >> 5;
        bb[q] = p & 31;
        size_t sidx = (size_t)(2 * layer + dir) * BATCH * HID +
                      (size_t)bb[q] * HID + cb * 16 + uu[q];
        cst[q] = c0[sidx];
        float hv = h0[sidx];
        __nv_bfloat16 hh = __float2bfloat16_rn(hv);
        __nv_bfloat16 hl = __float2bfloat16_rn(hv - __bfloat162float(hh));
        int gk = cb * 16 + uu[q];
        g_hB[dir][0][0][bb[q] * 1024 + gk] = hh;
        g_hB[dir][0][1][bb[q] * 1024 + gk] = hl;
    }

    // preload W ring (kt=0..3) + gx for t=0
    uint4 pw[4][4];   // [ring slot][j]  j = ml*2 + plane
#pragma unroll
    for (int s = 0; s < 4; s++)
#pragma unroll
        for (int j = 0; j < 4; j++)
            pw[s][j] = wfrag[s * 128 + j];
    float gxv[2][4];
    {
        const int te0 = dir ? (T_STEPS - 1) : 0;
        const float* gxs = gxd + (size_t)te0 * BATCH * GDIM;
#pragma unroll
        for (int q = 0; q < 2; q++)
#pragma unroll
            for (int g = 0; g < 4; g++)
                gxv[q][g] = __ldcs(gxs + (size_t)bb[q] * GDIM + g * HID + cb * 16 + uu[q]);
    }

    unsigned sense = 0;
    grid_barrier(dir, sense);   // publish initial h

    // ldsm B address components (batches 0-15 and 16-31)
    const int qq = lane >> 3, nf = qq >> 1, kl = qq & 1;
    const uint32_t brow0 = (uint32_t)((nf * 8 + (lane & 7)) * 128 + kl * 16);
    const uint32_t brow1 = brow0 + 16 * 128;

    for (int t = 0; t < T_STEPS; t++) {
        const int par = t & 1;
        const int te  = dir ? (T_STEPS - 1 - t) : t;

        // stage h (2 planes x 64KB) into SW128 k64-blocks (L2-coherent loads)
        {
            const uint4* hsrc = (const uint4*)&g_hB[dir][par][0][0];
#pragma unroll
            for (int i = 0; i < 32; i++) {
                int v = tid + i * 256;
                int plane = v >> 12;
                int w = v & 4095;
                int b = w >> 7;
                int kx = w & 127;
                int blk = kx >> 3, cq = kx & 7;
                uint4 d = __ldcg(hsrc + v);
                *(uint4*)(sm + plane * 65536 + blk * 4096 +
                          SW128((uint32_t)(b * 128 + cq * 16))) = d;
            }
        }
        __syncthreads();   // h staged; also guards Gp reuse from prev step

        float acc[2][4][4];
#pragma unroll
        for (int m = 0; m < 2; m++)
#pragma unroll
            for (int s = 0; s < 4; s++)
#pragma unroll
                for (int e = 0; e < 4; e++) acc[m][s][e] = 0.0f;

#pragma unroll
        for (int kt = 0; kt < 16; kt++) {
            const int rs = kt & 3;
            uint4 w0h = pw[rs][0], w0l = pw[rs][1];
            uint4 w1h = pw[rs][2], w1l = pw[rs][3];
            if (kt + 4 < 16) {
#pragma unroll
                for (int j = 0; j < 4; j++)
                    pw[rs][j] = wfrag[(kt + 4) * 128 + j];
            }
            const uint32_t blkoff = (uint32_t)((kq * 4 + (kt >> 2)) * 4096);
            const uint32_t cs = (uint32_t)((kt & 3) * 32);
            uint32_t bh0[4], bh1[4], bl0[4], bl1[4];
            LDSM4(bh0, smb + RSM_HA + blkoff + SW128(brow0 + cs));
            LDSM4(bh1, smb + RSM_HA + blkoff + SW128(brow1 + cs));
            LDSM4(bl0, smb + RSM_HB + blkoff + SW128(brow0 + cs));
            LDSM4(bl1, smb + RSM_HB + blkoff + SW128(brow1 + cs));
            {
                uint32_t ah[4] = {w0h.x, w0h.y, w0h.z, w0h.w};
                uint32_t al[4] = {w0l.x, w0l.y, w0l.z, w0l.w};
                MMA_BF16(acc[0][0], ah, bh0[0], bh0[1]);
                MMA_BF16(acc[0][0], ah, bl0[0], bl0[1]);
                MMA_BF16(acc[0][0], al, bh0[0], bh0[1]);
                MMA_BF16(acc[0][1], ah, bh0[2], bh0[3]);
                MMA_BF16(acc[0][1], ah, bl0[2], bl0[3]);
                MMA_BF16(acc[0][1], al, bh0[2], bh0[3]);
                MMA_BF16(acc[0][2], ah, bh1[0], bh1[1]);
                MMA_BF16(acc[0][2], ah, bl1[0], bl1[1]);
                MMA_BF16(acc[0][2], al, bh1[0], bh1[1]);
                MMA_BF16(acc[0][3], ah, bh1[2], bh1[3]);
                MMA_BF16(acc[0][3], ah, bl1[2], bl1[3]);
                MMA_BF16(acc[0][3], al, bh1[2], bh1[3]);
            }
            {
                uint32_t ah[4] = {w1h.x, w1h.y, w1h.z, w1h.w};
                uint32_t al[4] = {w1l.x, w1l.y, w1l.z, w1l.w};
                MMA_BF16(acc[1][0], ah, bh0[0], bh0[1]);
                MMA_BF16(acc[1][0], ah, bl0[0], bl0[1]);
                MMA_BF16(acc[1][0], al, bh0[0], bh0[1]);
                MMA_BF16(acc[1][1], ah, bh0[2], bh0[3]);
                MMA_BF16(acc[1][1], ah, bl0[2], bl0[3]);
                MMA_BF16(acc[1][1], al, bh0[2], bh0[3]);
                MMA_BF16(acc[1][2], ah, bh1[0], bh1[1]);
                MMA_BF16(acc[1][2], ah, bl1[0], bl1[1]);
                MMA_BF16(acc[1][2], al, bh1[0], bh1[1]);
                MMA_BF16(acc[1][3], ah, bh1[2], bh1[3]);
                MMA_BF16(acc[1][3], ah, bl1[2], bl1[3]);
                MMA_BF16(acc[1][3], al, bh1[2], bh1[3]);
            }
        }

        // write K-quarter partial G fragments (2 mi per warp)
        {
            float* Gk = Gp + kq * (64 * 33);
            int rr = lane >> 2;
            int cc = (lane & 3) * 2;
#pragma unroll
            for (int m = 0; m < 2; m++) {
                int r0 = (mh * 2 + m) * 16 + rr;
#pragma unroll
                for (int s = 0; s < 4; s++) {
                    int col = (s >> 1) * 16 + (s & 1) * 8 + cc;
                    Gk[r0 * 33 + col]           = acc[m][s][0];
                    Gk[r0 * 33 + col + 1]       = acc[m][s][1];
                    Gk[(r0 + 8) * 33 + col]     = acc[m][s][2];
                    Gk[(r0 + 8) * 33 + col + 1] = acc[m][s][3];
                }
            }
        }
        __syncthreads();

        // gate combine (sum 4 K-quarter partials) + state update + outputs
#pragma unroll
        for (int q = 0; q < 2; q++) {
            int u = uu[q], b = bb[q];
            float gsum[4];
#pragma unroll
            for (int g = 0; g < 4; g++) {
                int off = (g * 16 + u) * 33 + b;
                gsum[g] = (Gp[off] + Gp[off + 2112]) +
                          (Gp[off + 2 * 2112] + Gp[off + 3 * 2112]) + gxv[q][g];
            }
            float iv = hsig (gsum[0]);
            float fv = hsig (gsum[1]);
            float gv = clip1(gsum[2]);
            float ov = hsig (gsum[3]);
            float c  = fv * cst[q] + iv * gv;
            cst[q]   = c;
            float h  = ov * clip1(c);
            __nv_bfloat16 hh = __float2bfloat16_rn(h);
            __nv_bfloat16 hl = __float2bfloat16_rn(h - __bfloat162float(hh));
            int gk = cb * 16 + u;
            g_hB[dir][par ^ 1][0][b * 1024 + gk] = hh;
            g_hB[dir][par ^ 1][1][b * 1024 + gk] = hl;
            if (yfp) yfp[(size_t)te * BATCH * YW + (size_t)b * YW + dir * HID + gk] = h;
            if (yhi) {
                size_t ai = (size_t)(te * BATCH + b) * YW + dir * HID + gk;
                yhi[ai] = hh;
                ylo[ai] = hl;
            }
        }

        if (t < T_STEPS - 1) {
            // prefetch next step's W ring + gx BEFORE waiting at the barrier
#pragma unroll
            for (int s = 0; s < 4; s++)
#pragma unroll
                for (int j = 0; j < 4; j++)
                    pw[s][j] = wfrag[s * 128 + j];
            {
                const int ten = dir ? (T_STEPS - 2 - t) : (t + 1);
                const float* gxs = gxd + (size_t)ten * BATCH * GDIM;
#pragma unroll
                for (int q = 0; q < 2; q++)
#pragma unroll
                    for (int g = 0; g < 4; g++)
                        gxv[q][g] = __ldcs(gxs + (size_t)bb[q] * GDIM + g * HID + cb * 16 + uu[q]);
            }
            grid_barrier(dir, sense);
        }
    }
}

// ---------------- launch ----------------
extern "C" void kernel_launch(void* const* d_in, const int* in_sizes, int n_in,
                              void* d_out, int out_size)
{
    (void)in_sizes; (void)n_in; (void)out_size;

    const float* x  = (const float*)d_in[0];
    const float* h0 = (const float*)d_in[1];
    const float* c0 = (const float*)d_in[2];
    const float* P[24];
    for (int i = 0; i < 24; i++) P[i] = (const float*)d_in[3 + i];
    // P[(l*2+d)*4 + {0:w_ih, 1:w_hh, 2:b_ih, 3:b_hh}]

    float *gx = nullptr;
    __nv_bfloat16 *whi = nullptr, *wlo = nullptr, *ahi = nullptr, *alo = nullptr;
    uint4* wrec = nullptr;
    cudaGetSymbolAddress((void**)&gx,   g_gx);
    cudaGetSymbolAddress((void**)&whi,  g_whi);
    cudaGetSymbolAddress((void**)&wlo,  g_wlo);
    cudaGetSymbolAddress((void**)&ahi,  g_ahi);
    cudaGetSymbolAddress((void**)&alo,  g_alo);
    cudaGetSymbolAddress((void**)&wrec, g_wrec);
    cudaFuncSetAttribute(rec_kernel, cudaFuncAttributeMaxDynamicSharedMemorySize, REC3_SMEM);
    cudaFuncSetAttribute(gemm_mma,   cudaFuncAttributeMaxDynamicSharedMemorySize, GEMM_SMEM);

    float* out = (float*)d_out;

    // launch 1: bake W_hh fragment streams
    W6 w6;
    for (int i = 0; i < 6; i++) w6.w[i] = P[i * 4 + 1];
    wrec_prep<<<dim3(64, 6), 256>>>(w6, wrec);

    // launch 2: split all 6 w_ih
    W6 w6i;
    for (int i = 0; i < 6; i++) w6i.w[i] = P[i * 4];
    wih_split<<<dim3(8192, 6), 256>>>(w6i, whi, wlo);

    const size_t woff[6] = {0, 1310720, 2621440, 11010048, 19398656, 27787264};
    dim3 gg(GDIM / 128, MROWS / 128, 2), gb(256);

    // launch 3: layer 0 GEMM (K=320, fp32 x converted in staging)
    gemm_mma<<<gg, gb, GEMM_SMEM>>>(320, x, nullptr, nullptr,
                                    whi + woff[0], wlo + woff[0], whi + woff[1], wlo + woff[1],
                                    P[2], P[3], P[6], P[7], gx);
    // launch 4: layer 0 recurrence (writes layer-1 activations bf16)
    rec_kernel<<<128, 256, REC3_SMEM>>>(wrec, h0, c0, 0, gx, nullptr, ahi, alo);

    // launch 5: layer 1 GEMM (pipelined)
    gemm_mma<<<gg, gb, GEMM_SMEM>>>(2048, nullptr, ahi, alo,
                                    whi + woff[2], wlo + woff[2], whi + woff[3], wlo + woff[3],
                                    P[10], P[11], P[14], P[15], gx);
    // launch 6: layer 1 recurrence  <-- ncu -s 5 -c 1 captures this
    rec_kernel<<<128, 256, REC3_SMEM>>>(wrec, h0, c0, 1, gx, nullptr, ahi, alo);

    // launch 7: layer 2 GEMM (pipelined)
    gemm_mma<<<gg, gb, GEMM_SMEM>>>(2048, nullptr, ahi, alo,
                                    whi + woff[4], wlo + woff[4], whi + woff[5], wlo + woff[5],
                                    P[18], P[19], P[22], P[23], gx);
    // launch 8: layer 2 recurrence -> fp32 output
    rec_kernel<<<128, 256, REC3_SMEM>>>(wrec, h0, c0, 2, gx, out, nullptr, nullptr);
}

// round 14
// speedup vs baseline: 1.8305x; 1.8305x over previous
#include <cuda_runtime.h>
#include <cuda_fp16.h>
#include <cstdint>
#include <cstddef>

#define T_STEPS 512
#define BATCH   32
#define HID     1024
#define GDIM    4096
#define MROWS   16384          // T*B
#define YW      2048           // 2*H

typedef unsigned long long ull;

// ---------------- device scratch (no runtime allocation) ----------------
__device__ float g_gx[134217728];          // [2][MROWS][GDIM]  512 MB
__device__ __half g_hH[2][2][32 * 1024];   // [dir][parity][b*1024+k] fp16
__device__ unsigned g_bar_cnt[2]   = {0, 0};
__device__ unsigned g_bar_phase[2] = {0, 0};
__device__ __half g_wih[36700160];         // w_ih fp16 (all 6)
__device__ __half g_act[33554432];         // activations fp16 [16384 x 2048]
// W_hh baked per-thread fragment streams (8 warps = 4 mi x 2 kh):
// [ld 6][cb 64][wr 8][kt 32][lane 32] x 16B (one fp16 A-fragment)
__device__ uint4 g_wrec[3145728];          // 48 MB

// ---------------- helpers ----------------
__device__ __forceinline__ uint32_t smem_u32(const void* p) {
    uint32_t a;
    asm("{ .reg .u64 t; cvta.to.shared.u64 t, %1; cvt.u32.u64 %0, t; }" : "=r"(a) : "l"(p));
    return a;
}
#define SW128(o) ((o) ^ (((o) >> 3) & 0x70))

#define MMA_F16(d, a, b0v, b1v)                                               \
    asm volatile("mma.sync.aligned.m16n8k16.row.col.f32.f16.f16.f32 "         \
        "{%0,%1,%2,%3}, {%4,%5,%6,%7}, {%8,%9}, {%0,%1,%2,%3};"               \
        : "+f"((d)[0]), "+f"((d)[1]), "+f"((d)[2]), "+f"((d)[3])              \
        : "r"((a)[0]), "r"((a)[1]), "r"((a)[2]), "r"((a)[3]),                 \
          "r"(b0v), "r"(b1v))

#define LDSM4(r, addr)                                                        \
    asm volatile("ldmatrix.sync.aligned.m8n8.x4.shared.b16 "                  \
        "{%0,%1,%2,%3}, [%4];"                                                \
        : "=r"((r)[0]), "=r"((r)[1]), "=r"((r)[2]), "=r"((r)[3])              \
        : "r"(addr))

#define CP_ASYNC16(smaddr, gaddr)                                             \
    asm volatile("cp.async.cg.shared.global [%0], [%1], 16;"                  \
        :: "r"(smaddr), "l"(gaddr) : "memory")
#define CP_COMMIT() asm volatile("cp.async.commit_group;" ::: "memory")
#define CP_WAIT0()  asm volatile("cp.async.wait_group 0;" ::: "memory")
#define CP_WAIT1()  asm volatile("cp.async.wait_group 1;" ::: "memory")

__device__ __forceinline__ float hsig(float v)  { return fminf(fmaxf(fmaf(v, 0.2f, 0.5f), 0.0f), 1.0f); }
__device__ __forceinline__ float clip1(float v) { return fminf(fmaxf(v, -1.0f), 1.0f); }

// sense-reversing grid barrier (proven R9 form)
__device__ __forceinline__ void grid_barrier(int dir, unsigned& sense) {
    __syncthreads();
    sense ^= 1u;
    if (threadIdx.x == 0) {
        unsigned prev;
        asm volatile("atom.add.acq_rel.gpu.u32 %0, [%1], 1;"
                     : "=r"(prev) : "l"(&g_bar_cnt[dir]) : "memory");
        if (prev == 63u) {
            asm volatile("st.relaxed.gpu.u32 [%0], %1;"
                         :: "l"(&g_bar_cnt[dir]), "r"(0u) : "memory");
            unsigned dummy;
            asm volatile("atom.exch.release.gpu.b32 %0, [%1], %2;"
                         : "=r"(dummy) : "l"(&g_bar_phase[dir]), "r"(sense) : "memory");
        } else {
            unsigned ph;
            do {
                __nanosleep(64);
                asm volatile("ld.acquire.gpu.u32 %0, [%1];"
                             : "=r"(ph) : "l"(&g_bar_phase[dir]) : "memory");
            } while (ph != sense);
        }
    }
    __syncthreads();
}

// ---------------- W_hh prep: bake fp16 fragment streams ----------------
// Rec warp layout: wr(0..7) -> mi = wr>>1 (gate tile), kh = wr&1 (K half).
struct W6 { const float* w[6]; };

__global__ void __launch_bounds__(256)
wrec_prep(W6 p, uint4* __restrict__ out)
{
    const int cb = blockIdx.x;
    const int ld = blockIdx.y;
    const float* __restrict__ w = p.w[ld];
    for (int it = 0; it < 32; it++) {
        int v    = it * 256 + threadIdx.x;   // 0..8191 = 8 wr x 32 kt x 32 lanes
        int wr   = v >> 10;
        int kt   = (v >> 5) & 31;
        int lane = v & 31;
        int mi = wr >> 1, kh = wr & 1;
        unsigned short fr[8];
#pragma unroll
        for (int j = 0; j < 4; j++) {
            int r  = (lane >> 2) + (j & 1) * 8;
            int kc = (lane & 3) * 2 + (j >> 1) * 8;
            int row = mi * HID + cb * 16 + r;
            int k   = kh * 512 + kt * 16 + kc;
#pragma unroll
            for (int e = 0; e < 2; e++) {
                __half h = __float2half_rn(w[(size_t)row * HID + k + e]);
                fr[j * 2 + e] = *(unsigned short*)&h;
            }
        }
        out[(((size_t)(ld * 64 + cb) * 8 + wr) * 32 + kt) * 32 + lane] = *(uint4*)fr;
    }
}

// ---------------- w_ih fp16 conversion (all 6 in one launch) ----------------
__global__ void __launch_bounds__(256)
wih_split(W6 p, __half* __restrict__ out_base)
{
    const int ld = blockIdx.y;
    const size_t woff = (ld == 0) ? 0u :
                        (ld == 1) ? 1310720u :
                        (size_t)2621440u + (size_t)(ld - 2) * 8388608u;
    const int n4 = (ld < 2) ? 327680 : 2097152;
    int i = blockIdx.x * 256 + threadIdx.x;
    if (i >= n4) return;
    float4 v = ((const float4*)p.w[ld])[i];
    __half2* O = (__half2*)(out_base + woff) + i * 2;
    O[0] = __half2(__float2half_rn(v.x), __float2half_rn(v.y));
    O[1] = __half2(__float2half_rn(v.z), __float2half_rn(v.w));
}

// ---------------- tensor-core input-projection GEMM (fp16, 2-stage cp.async) ----------------
#define SMO_A 0
#define SMO_B 16384
#define STAGE_BYTES 32768
#define SMO_BIAS 65536
#define GEMM_SMEM (65536 + 512)

__global__ void __launch_bounds__(256)
gemm_mma(int K, const float* __restrict__ Afp,
         const __half* __restrict__ Ah,
         const __half* __restrict__ WF, const __half* __restrict__ WR,
         const float* __restrict__ bf1, const float* __restrict__ bf2,
         const float* __restrict__ br1, const float* __restrict__ br2,
         float* __restrict__ G)
{
    extern __shared__ char sm[];
    const uint32_t smb = smem_u32(sm);
    const int tid  = threadIdx.x;
    const int wid  = tid >> 5;
    const int lane = tid & 31;
    const int z    = blockIdx.z;

    const __half* __restrict__ W  = z ? WR  : WF;
    const float* __restrict__ b1 = z ? br1 : bf1;
    const float* __restrict__ b2 = z ? br2 : bf2;
    float* __restrict__ Gz = G + (size_t)z * MROWS * GDIM;

    const int n0 = blockIdx.x * 128;
    const int m0 = blockIdx.y * 128;
    const int wm = (wid >> 2) * 64;
    const int wn = (wid & 3) * 32;

    {
        float* bias = (float*)(sm + SMO_BIAS);
        if (tid < 128) bias[tid] = b1[n0 + tid] + b2[n0 + tid];
    }

    float acc[4][4][4];
#pragma unroll
    for (int mi = 0; mi < 4; mi++)
#pragma unroll
        for (int ni = 0; ni < 4; ni++)
#pragma unroll
            for (int e = 0; e < 4; e++) acc[mi][ni][e] = 0.0f;

    const int nk = K >> 6;

    int srow[4], scol[4];
    uint32_t soff[4];
#pragma unroll
    for (int i = 0; i < 4; i++) {
        int v = tid + i * 256;
        srow[i] = v >> 3;
        scol[i] = (v & 7) * 8;
        soff[i] = SW128((uint32_t)(srow[i] * 128 + (v & 7) * 16));
    }

#define GEMM_MMA_CHUNK(SB)                                                    \
    {                                                                         \
        _Pragma("unroll")                                                     \
        for (int ks = 0; ks < 4; ks++) {                                      \
            uint32_t ah[4][4], bh[2][4];                                      \
            _Pragma("unroll")                                                 \
            for (int mi = 0; mi < 4; mi++) {                                  \
                uint32_t off = SW128((uint32_t)(                              \
                    (wm + mi * 16 + (lane & 15)) * 128 + ks * 32 + (lane >> 4) * 16)); \
                LDSM4(ah[mi], smb + (SB) + SMO_A + off);                      \
            }                                                                 \
            _Pragma("unroll")                                                 \
            for (int p = 0; p < 2; p++) {                                     \
                int q  = lane >> 3;                                           \
                int nf = q >> 1, kl = q & 1;                                  \
                uint32_t off = SW128((uint32_t)(                              \
                    (wn + p * 16 + nf * 8 + (lane & 7)) * 128 + ks * 32 + kl * 16)); \
                LDSM4(bh[p], smb + (SB) + SMO_B + off);                       \
            }                                                                 \
            _Pragma("unroll")                                                 \
            for (int mi = 0; mi < 4; mi++) {                                  \
                _Pragma("unroll")                                             \
                for (int ni = 0; ni < 4; ni++) {                              \
                    const int p = ni >> 1, s = (ni & 1) * 2;                  \
                    MMA_F16(acc[mi][ni], ah[mi], bh[p][s], bh[p][s + 1]);     \
                }                                                             \
            }                                                                 \
        }                                                                     \
    }

    if (Afp) {
        // synchronous path (layer 0, K=320): convert fp32 A during staging
        for (int ch = 0; ch < nk; ch++) {
            const int kc = ch * 64;
            __syncthreads();
#pragma unroll
            for (int i = 0; i < 4; i++) {
                size_t ga = (size_t)(m0 + srow[i]) * K + kc + scol[i];
                size_t gb = (size_t)(n0 + srow[i]) * K + kc + scol[i];
                float4 f0 = *(const float4*)(Afp + ga);
                float4 f1 = *(const float4*)(Afp + ga + 4);
                float fv[8] = {f0.x, f0.y, f0.z, f0.w, f1.x, f1.y, f1.z, f1.w};
                unsigned short hh[8];
#pragma unroll
                for (int j = 0; j < 8; j++) {
                    __half h = __float2half_rn(fv[j]);
                    hh[j] = *(unsigned short*)&h;
                }
                *(uint4*)(sm + SMO_A + soff[i]) = *(uint4*)hh;
                *(uint4*)(sm + SMO_B + soff[i]) = *(const uint4*)(W + gb);
            }
            __syncthreads();
            GEMM_MMA_CHUNK(0u)
        }
    } else {
#define GEMM_STAGE(CH, PB)                                                    \
        {                                                                     \
            const int kc_ = (CH) * 64;                                        \
            const uint32_t sb_ = (uint32_t)(PB) * STAGE_BYTES;                \
            _Pragma("unroll")                                                 \
            for (int i = 0; i < 4; i++) {                                     \
                size_t ga = (size_t)(m0 + srow[i]) * K + kc_ + scol[i];       \
                size_t gb = (size_t)(n0 + srow[i]) * K + kc_ + scol[i];       \
                CP_ASYNC16(smb + sb_ + SMO_A + soff[i], Ah + ga);             \
                CP_ASYNC16(smb + sb_ + SMO_B + soff[i], W + gb);              \
            }                                                                 \
        }
        GEMM_STAGE(0, 0)
        CP_COMMIT();
        for (int ch = 0; ch < nk; ch++) {
            if (ch + 1 < nk) {
                GEMM_STAGE(ch + 1, (ch + 1) & 1)
                CP_COMMIT();
                CP_WAIT1();
            } else {
                CP_WAIT0();
            }
            __syncthreads();
            const uint32_t sb = (uint32_t)(ch & 1) * STAGE_BYTES;
            GEMM_MMA_CHUNK(sb)
            __syncthreads();
        }
#undef GEMM_STAGE
    }

    const float* bias = (const float*)(sm + SMO_BIAS);
    const int qr = lane >> 2;
    const int qc = (lane & 3) * 2;
#pragma unroll
    for (int mi = 0; mi < 4; mi++) {
#pragma unroll
        for (int ni = 0; ni < 4; ni++) {
            int col = wn + ni * 8 + qc;
            float bx = bias[col], by = bias[col + 1];
            size_t base0 = (size_t)(m0 + wm + mi * 16 + qr) * GDIM + n0 + col;
            size_t base1 = base0 + (size_t)8 * GDIM;
            *(float2*)&Gz[base0] = make_float2(acc[mi][ni][0] + bx, acc[mi][ni][1] + by);
            *(float2*)&Gz[base1] = make_float2(acc[mi][ni][2] + bx, acc[mi][ni][3] + by);
        }
    }
}

// ---------------- persistent fp16 tensor-core recurrence ----------------
// 128 CTAs x 256 threads. dir = blockIdx.x>>6; CTA owns 16 units (64 gate rows).
// Warp wr: mi = wr>>1 (gate tile), kh = wr&1 (K half). Warp = m16 x n32 x K512.
// Single fp16 plane; W depth-8 register ring; gx staged coalesced into smem.
#define RSM_H  0
#define RSM_G  65536
#define RSM_GX (65536 + 2*64*33*4)              // 82432
#define REC_SMEM (82432 + 32*68*4)              // 91136 B

__global__ void __launch_bounds__(256)
rec_kernel(const uint4* __restrict__ wrec,
           const float* __restrict__ h0, const float* __restrict__ c0,
           int layer, const float* __restrict__ gx,
           float* __restrict__ yfp, __half* __restrict__ yh)
{
    extern __shared__ char sm[];
    const uint32_t smb = smem_u32(sm);
    float* G0 = (float*)(sm + RSM_G);          // [64][33] K-half 0
    float* G1 = G0 + 64 * 33;                  // [64][33] K-half 1
    float* gxbuf = (float*)(sm + RSM_GX);      // [32][68]

    const int tid  = threadIdx.x;
    const int lane = tid & 31;
    const int wrp  = tid >> 5;
    const int mi   = wrp >> 1;
    const int kh   = wrp & 1;
    const int dir  = blockIdx.x >> 6;
    const int cb   = blockIdx.x & 63;
    const int ld   = layer * 2 + dir;
    const float* __restrict__ gxd = gx + (size_t)dir * MROWS * GDIM;
    const uint4* __restrict__ wfrag =
        wrec + ((size_t)(ld * 64 + cb) * 8 + wrp) * 1024 + lane;
    // per kt advance: 32 uint4

    // c-state: 2 (unit,batch) pairs per thread
    float cst[2];
    int uu[2], bb[2];
#pragma unroll
    for (int q = 0; q < 2; q++) {
        int p = q * 256 + tid;
        uu[q] = p >> 5;
        bb[q] = p & 31;
        size_t sidx = (size_t)(2 * layer + dir) * BATCH * HID +
                      (size_t)bb[q] * HID + cb * 16 + uu[q];
        cst[q] = c0[sidx];
        g_hH[dir][0][bb[q] * 1024 + cb * 16 + uu[q]] = __float2half_rn(h0[sidx]);
    }

    // preload W ring (kt=0..7)
    uint4 pw[8];
#pragma unroll
    for (int s = 0; s < 8; s++) pw[s] = wfrag[s * 32];

    unsigned sense = 0;
    grid_barrier(dir, sense);   // publish initial h

    // gx staging coords: 2 float4 per thread
    int gxb[2], gxg[2], gxu[2];
#pragma unroll
    for (int j = 0; j < 2; j++) {
        int v4 = tid + j * 256;
        gxb[j] = v4 >> 4;
        gxg[j] = (v4 & 15) >> 2;
        gxu[j] = (v4 & 3) * 4;
    }

    // ldsm B address components (batches 0-15 and 16-31)
    const int qq = lane >> 3, nf = qq >> 1, kl = qq & 1;
    const uint32_t brow0 = (uint32_t)((nf * 8 + (lane & 7)) * 128 + kl * 16);
    const uint32_t brow1 = brow0 + 16 * 128;

    for (int t = 0; t < T_STEPS; t++) {
        const int par = t & 1;
        const int te  = dir ? (T_STEPS - 1 - t) : t;

        // stage gx (coalesced float4) + h (64KB fp16) into smem
        {
            const float* gxs = gxd + (size_t)te * BATCH * GDIM;
#pragma unroll
            for (int j = 0; j < 2; j++) {
                float4 d = *(const float4*)(gxs + (size_t)gxb[j] * GDIM +
                                            gxg[j] * HID + cb * 16 + gxu[j]);
                *(float4*)(gxbuf + gxb[j] * 68 + gxg[j] * 16 + gxu[j]) = d;
            }
            const uint4* hsrc = (const uint4*)&g_hH[dir][par][0];
#pragma unroll
            for (int i = 0; i < 16; i++) {
                int v = tid + i * 256;
                int b = v >> 7;
                int kx = v & 127;
                int blk = kx >> 3, cq = kx & 7;
                uint4 d = __ldcg(hsrc + v);
                *(uint4*)(sm + blk * 4096 + SW128((uint32_t)(b * 128 + cq * 16))) = d;
            }
        }
        __syncthreads();   // h+gx staged; guards G/gx buffer reuse from prev step

        float acc[4][4];
#pragma unroll
        for (int s = 0; s < 4; s++)
#pragma unroll
            for (int e = 0; e < 4; e++) acc[s][e] = 0.0f;

#pragma unroll 8
        for (int kt = 0; kt < 32; kt++) {
            const int rs = kt & 7;
            uint32_t a[4] = {pw[rs].x, pw[rs].y, pw[rs].z, pw[rs].w};
            if (kt + 8 < 32) pw[rs] = wfrag[(kt + 8) * 32];
            const uint32_t blkoff = (uint32_t)((kh * 8 + (kt >> 2)) * 4096);
            const uint32_t cs = (uint32_t)((kt & 3) * 32);
            uint32_t b0[4], b1[4];
            LDSM4(b0, smb + RSM_H + blkoff + SW128(brow0 + cs));
            LDSM4(b1, smb + RSM_H + blkoff + SW128(brow1 + cs));
            MMA_F16(acc[0], a, b0[0], b0[1]);
            MMA_F16(acc[1], a, b0[2], b0[3]);
            MMA_F16(acc[2], a, b1[0], b1[1]);
            MMA_F16(acc[3], a, b1[2], b1[3]);
        }

        // write K-half partial G fragments
        {
            float* Gk = kh ? G1 : G0;
            int r0 = mi * 16 + (lane >> 2);
            int cc = (lane & 3) * 2;
#pragma unroll
            for (int s = 0; s < 4; s++) {
                int col = (s >> 1) * 16 + (s & 1) * 8 + cc;
                Gk[r0 * 33 + col]           = acc[s][0];
                Gk[r0 * 33 + col + 1]       = acc[s][1];
                Gk[(r0 + 8) * 33 + col]     = acc[s][2];
                Gk[(r0 + 8) * 33 + col + 1] = acc[s][3];
            }
        }
        __syncthreads();

        // gate combine + state update + outputs
#pragma unroll
        for (int q = 0; q < 2; q++) {
            int u = uu[q], b = bb[q];
            float iv = hsig (G0[( 0 + u) * 33 + b] + G1[( 0 + u) * 33 + b] + gxbuf[b * 68 + 0 * 16 + u]);
            float fv = hsig (G0[(16 + u) * 33 + b] + G1[(16 + u) * 33 + b] + gxbuf[b * 68 + 1 * 16 + u]);
            float gv = clip1(G0[(32 + u) * 33 + b] + G1[(32 + u) * 33 + b] + gxbuf[b * 68 + 2 * 16 + u]);
            float ov = hsig (G0[(48 + u) * 33 + b] + G1[(48 + u) * 33 + b] + gxbuf[b * 68 + 3 * 16 + u]);
            float c  = fv * cst[q] + iv * gv;
            cst[q]   = c;
            float h  = ov * clip1(c);
            int gk = cb * 16 + u;
            g_hH[dir][par ^ 1][b * 1024 + gk] = __float2half_rn(h);
            if (yfp) yfp[(size_t)te * BATCH * YW + (size_t)b * YW + dir * HID + gk] = h;
            if (yh)  yh[(size_t)(te * BATCH + b) * YW + dir * HID + gk] = __float2half_rn(h);
        }

        if (t < T_STEPS - 1) {
            // prefetch next step's W ring BEFORE waiting at the barrier
#pragma unroll
            for (int s = 0; s < 8; s++) pw[s] = wfrag[s * 32];
            grid_barrier(dir, sense);
        }
    }
}

// ---------------- launch ----------------
extern "C" void kernel_launch(void* const* d_in, const int* in_sizes, int n_in,
                              void* d_out, int out_size)
{
    (void)in_sizes; (void)n_in; (void)out_size;

    const float* x  = (const float*)d_in[0];
    const float* h0 = (const float*)d_in[1];
    const float* c0 = (const float*)d_in[2];
    const float* P[24];
    for (int i = 0; i < 24; i++) P[i] = (const float*)d_in[3 + i];
    // P[(l*2+d)*4 + {0:w_ih, 1:w_hh, 2:b_ih, 3:b_hh}]

    float* gxp = nullptr;
    __half *wih = nullptr, *act = nullptr;
    uint4* wrec = nullptr;
    cudaGetSymbolAddress((void**)&gxp,  g_gx);
    cudaGetSymbolAddress((void**)&wih,  g_wih);
    cudaGetSymbolAddress((void**)&act,  g_act);
    cudaGetSymbolAddress((void**)&wrec, g_wrec);
    cudaFuncSetAttribute(rec_kernel, cudaFuncAttributeMaxDynamicSharedMemorySize, REC_SMEM);
    cudaFuncSetAttribute(gemm_mma,   cudaFuncAttributeMaxDynamicSharedMemorySize, GEMM_SMEM);

    float* out = (float*)d_out;

    // launch 1: bake W_hh fp16 fragment streams
    W6 w6;
    for (int i = 0; i < 6; i++) w6.w[i] = P[i * 4 + 1];
    wrec_prep<<<dim3(64, 6), 256>>>(w6, wrec);

    // launch 2: convert all 6 w_ih to fp16
    W6 w6i;
    for (int i = 0; i < 6; i++) w6i.w[i] = P[i * 4];
    wih_split<<<dim3(8192, 6), 256>>>(w6i, wih);

    const size_t woff[6] = {0, 1310720, 2621440, 11010048, 19398656, 27787264};
    dim3 gg(GDIM / 128, MROWS / 128, 2), gb(256);

    // layer 0 (K=320, fp32 x converted in staging)
    gemm_mma<<<gg, gb, GEMM_SMEM>>>(320, x, nullptr,
                                    wih + woff[0], wih + woff[1],
                                    P[2], P[3], P[6], P[7], gxp);
    rec_kernel<<<128, 256, REC_SMEM>>>(wrec, h0, c0, 0, gxp, nullptr, act);

    // layer 1 (K=2048, pipelined)
    gemm_mma<<<gg, gb, GEMM_SMEM>>>(2048, nullptr, act,
                                    wih + woff[2], wih + woff[3],
                                    P[10], P[11], P[14], P[15], gxp);
    rec_kernel<<<128, 256, REC_SMEM>>>(wrec, h0, c0, 1, gxp, nullptr, act);

    // layer 2 (K=2048, pipelined) -> fp32 output
    gemm_mma<<<gg, gb, GEMM_SMEM>>>(2048, nullptr, act,
                                    wih + woff[4], wih + woff[5],
                                    P[18], P[19], P[22], P[23], gxp);
    rec_kernel<<<128, 256, REC_SMEM>>>(wrec, h0, c0, 2, gxp, out, nullptr);
}